// round 10
// baseline (speedup 1.0000x reference)
#include <cuda_runtime.h>
#include <cuda_fp16.h>
#include <math.h>

#define BATCH 256
#define SEQT  512
#define VOCAB 50000
#define EMB   300
#define HID   256
#define GATES 1024   // 4*HID
#define NBLK  128
// sWb (32768 u32 = 128KB fp16 frags) + sh2 (16*132 u32)
#define SMEM_RNN (32768*4 + 2112*4)

// Scratch (static device memory — allocation-free)
__device__ float    d_proj[VOCAB][2*GATES];    // [v][dir*1024 + hc*4 + g], bias folded in
__device__ unsigned d_hbuf[2][2][BATCH][132];  // fp16 pairs, k-permuted
__device__ float    d_hfinal[2][BATCH][HID];   // fp32 final hidden state
__device__ int      d_len[BATCH];

__device__ __forceinline__ float tanha(float x){
    float y; asm("tanh.approx.f32 %0, %1;" : "=f"(y) : "f"(x)); return y;
}
__device__ __forceinline__ float sigt(float x){
    return fmaf(tanha(0.5f*x), 0.5f, 0.5f);
}
// pair-permutation inside a 16-k block: pair j -> slot (j&3)*2 + (j>>2)
__device__ __forceinline__ int hslot(int k){   // k even; returns u32 index
    int blk = k >> 4, j = (k & 15) >> 1;
    return blk*8 + (j & 3)*2 + (j >> 2);
}
__device__ __forceinline__ unsigned packh2(float a, float b){
    __half2 hv = __halves2half2(__float2half_rn(a), __float2half_rn(b));
    return *(unsigned*)&hv;
}

// one 16-k block of the recurrent MMA (4 gate mmas)
__device__ __forceinline__ void mma_kb(float acc[4][4], const unsigned* sh2,
                                       const unsigned* sWb, int kb,
                                       int rb0, int rb1, int qq, int wg, int lane){
    uint2 aA = *(const uint2*)&sh2[rb0*132 + kb*8 + qq*2];
    uint2 aB = *(const uint2*)&sh2[rb1*132 + kb*8 + qq*2];
    uint4 B01 = *(const uint4*)&sWb[        ((wg*16 + kb)*32 + lane)*4];
    uint4 B23 = *(const uint4*)&sWb[16384 + ((wg*16 + kb)*32 + lane)*4];
    asm volatile(
        "mma.sync.aligned.m16n8k16.row.col.f32.f16.f16.f32 "
        "{%0,%1,%2,%3},{%4,%5,%6,%7},{%8,%9},{%0,%1,%2,%3};"
        : "+f"(acc[0][0]), "+f"(acc[0][1]), "+f"(acc[0][2]), "+f"(acc[0][3])
        : "r"(aA.x), "r"(aB.x), "r"(aA.y), "r"(aB.y), "r"(B01.x), "r"(B01.y));
    asm volatile(
        "mma.sync.aligned.m16n8k16.row.col.f32.f16.f16.f32 "
        "{%0,%1,%2,%3},{%4,%5,%6,%7},{%8,%9},{%0,%1,%2,%3};"
        : "+f"(acc[1][0]), "+f"(acc[1][1]), "+f"(acc[1][2]), "+f"(acc[1][3])
        : "r"(aA.x), "r"(aB.x), "r"(aA.y), "r"(aB.y), "r"(B01.z), "r"(B01.w));
    asm volatile(
        "mma.sync.aligned.m16n8k16.row.col.f32.f16.f16.f32 "
        "{%0,%1,%2,%3},{%4,%5,%6,%7},{%8,%9},{%0,%1,%2,%3};"
        : "+f"(acc[2][0]), "+f"(acc[2][1]), "+f"(acc[2][2]), "+f"(acc[2][3])
        : "r"(aA.x), "r"(aB.x), "r"(aA.y), "r"(aB.y), "r"(B23.x), "r"(B23.y));
    asm volatile(
        "mma.sync.aligned.m16n8k16.row.col.f32.f16.f16.f32 "
        "{%0,%1,%2,%3},{%4,%5,%6,%7},{%8,%9},{%0,%1,%2,%3};"
        : "+f"(acc[3][0]), "+f"(acc[3][1]), "+f"(acc[3][2]), "+f"(acc[3][3])
        : "r"(aA.x), "r"(aB.x), "r"(aA.y), "r"(aB.y), "r"(B23.z), "r"(B23.w));
}

// ---------------------------------------------------------------------------
// Kernel 1: lengths + zero initial (permuted-fp16) h states
// ---------------------------------------------------------------------------
__global__ void k_init(const int* __restrict__ ids){
    int b = blockIdx.x;
    __shared__ int cnt;
    if (threadIdx.x == 0) cnt = 0;
    __syncthreads();
    int c = 0;
    for (int t = threadIdx.x; t < SEQT; t += blockDim.x)
        c += (ids[b*SEQT + t] != 0);
    #pragma unroll
    for (int o = 16; o; o >>= 1) c += __shfl_down_sync(0xffffffffu, c, o);
    if ((threadIdx.x & 31) == 0) atomicAdd(&cnt, c);
    __syncthreads();
    if (threadIdx.x == 0) d_len[b] = cnt;
    for (int i = threadIdx.x; i < 132; i += blockDim.x){
        d_hbuf[0][0][b][i] = 0u;
        d_hbuf[0][1][b][i] = 0u;
        d_hbuf[1][0][b][i] = 0u;
        d_hbuf[1][1][b][i] = 0u;
    }
}

// ---------------------------------------------------------------------------
// Kernel 2: vocab projection GEMM via tf32 mma. fp32 bits fed directly to the
// tf32 mma (HW truncates mantissa) — no cvt on the load path.
// ---------------------------------------------------------------------------
__global__ void __launch_bounds__(256, 2)
k_vgemm(const float* __restrict__ emb,
        const float* __restrict__ Wfw, const float* __restrict__ bfw,
        const float* __restrict__ Wbw, const float* __restrict__ bbw){
    __shared__ unsigned As[16][132];
    __shared__ unsigned Bs[16][132];
    int nx  = blockIdx.x;
    int dir = nx >> 3;
    int n0  = (nx & 7) * 128;
    int m0  = blockIdx.y * 128;
    const float* __restrict__ Wg = dir ? Wbw : Wfw;
    const float* __restrict__ bg = dir ? bbw : bfw;

    int t    = threadIdx.x;
    int lane = t & 31;
    int w    = t >> 5;
    int wm   = w & 1;
    int wn   = w >> 1;

    float acc[4][4][4] = {};

    for (int k0 = 0; k0 < 304; k0 += 16){
        {
            int kk = (t & 3) * 4;
            #pragma unroll
            for (int i = 0; i < 2; i++){
                int m  = (t >> 2) + i*64;
                int gm = m0 + m;
                float4 v = make_float4(0.f,0.f,0.f,0.f);
                if (gm < VOCAB && (k0 + kk + 4) <= EMB)
                    v = *(const float4*)&emb[(size_t)gm*EMB + k0 + kk];
                As[kk+0][m] = __float_as_uint(v.x);
                As[kk+1][m] = __float_as_uint(v.y);
                As[kk+2][m] = __float_as_uint(v.z);
                As[kk+3][m] = __float_as_uint(v.w);
            }
        }
        {
            int kk = t >> 4;
            int nn = (t & 15) * 8;
            float4 v0 = make_float4(0.f,0.f,0.f,0.f);
            float4 v1 = make_float4(0.f,0.f,0.f,0.f);
            if (k0 + kk < EMB){
                v0 = *(const float4*)&Wg[(size_t)(k0 + kk)*GATES + n0 + nn];
                v1 = *(const float4*)&Wg[(size_t)(k0 + kk)*GATES + n0 + nn + 4];
            }
            As[0][0] = As[0][0];  // no-op
            Bs[kk][nn+0] = __float_as_uint(v0.x); Bs[kk][nn+1] = __float_as_uint(v0.y);
            Bs[kk][nn+2] = __float_as_uint(v0.z); Bs[kk][nn+3] = __float_as_uint(v0.w);
            Bs[kk][nn+4] = __float_as_uint(v1.x); Bs[kk][nn+5] = __float_as_uint(v1.y);
            Bs[kk][nn+6] = __float_as_uint(v1.z); Bs[kk][nn+7] = __float_as_uint(v1.w);
        }
        __syncthreads();

        #pragma unroll
        for (int k8 = 0; k8 < 2; k8++){
            int k = k8*8 + (lane & 3);
            unsigned a[4][4], b[4][2];
            #pragma unroll
            for (int mi = 0; mi < 4; mi++){
                int row = wm*64 + mi*16 + (lane >> 2);
                a[mi][0] = As[k  ][row];
                a[mi][1] = As[k  ][row + 8];
                a[mi][2] = As[k+4][row];
                a[mi][3] = As[k+4][row + 8];
            }
            #pragma unroll
            for (int ni = 0; ni < 4; ni++){
                int n = wn*32 + ni*8 + (lane >> 2);
                b[ni][0] = Bs[k  ][n];
                b[ni][1] = Bs[k+4][n];
            }
            #pragma unroll
            for (int mi = 0; mi < 4; mi++)
                #pragma unroll
                for (int ni = 0; ni < 4; ni++)
                    asm volatile(
                        "mma.sync.aligned.m16n8k8.row.col.f32.tf32.tf32.f32 "
                        "{%0,%1,%2,%3},{%4,%5,%6,%7},{%8,%9},{%0,%1,%2,%3};"
                        : "+f"(acc[mi][ni][0]), "+f"(acc[mi][ni][1]),
                          "+f"(acc[mi][ni][2]), "+f"(acc[mi][ni][3])
                        : "r"(a[mi][0]), "r"(a[mi][1]), "r"(a[mi][2]), "r"(a[mi][3]),
                          "r"(b[ni][0]), "r"(b[ni][1]));
        }
        __syncthreads();
    }

    #pragma unroll
    for (int mi = 0; mi < 4; mi++){
        int rbase = m0 + wm*64 + mi*16 + (lane >> 2);
        #pragma unroll
        for (int ni = 0; ni < 4; ni++){
            int cbase = n0 + wn*32 + ni*8 + (lane & 3)*2;
            #pragma unroll
            for (int c = 0; c < 4; c++){
                int gm  = rbase + (c >> 1)*8;
                int col = cbase + (c & 1);
                if (gm >= VOCAB) continue;
                int g  = col >> 8;
                int hc = col & 255;
                d_proj[gm][dir*GATES + hc*4 + g] = acc[mi][ni][c] + bg[col];
            }
        }
    }
}

// ---------------------------------------------------------------------------
// Kernel 3: persistent bidirectional LSTM — cluster(4) skeleton (R9) with
// split-K schedule: local 4 kb MMA runs in the arrive->wait skew window
// (own h slice kept in local smem), only 12 peer kb staged after the wait.
// ---------------------------------------------------------------------------
__global__ void __launch_bounds__(256, 1) __cluster_dims__(4, 1, 1)
k_rnn(const float* __restrict__ Wfw, const float* __restrict__ Wbw,
      const int* __restrict__ ids){
    extern __shared__ unsigned smem_u[];
    unsigned* sWb = smem_u;            // 2 regions x [wg 0..7][kb][lane] uint4 fp16 B frags
    unsigned* sh2 = smem_u + 32768;    // [16][132] fp16 pairs, k-permuted

    int tid = threadIdx.x;
    int bid = blockIdx.x;
    int dir = bid >> 6;
    int tl  = bid & 63;
    int b0  = (tl >> 2) * 16;          // batch tile (16 rows)
    int rank = tl & 3;                 // cluster rank = hid tile
    int h0  = rank * 64;               // hid tile (64 cols)
    const float* __restrict__ Wg = dir ? Wbw : Wfw;

    int lane = tid & 31;
    int wg   = tid >> 5;    // warp id = hid group of 8 (0..7)
    int gid  = lane >> 2;
    int qq   = lane & 3;

    // ---- Fill Wh fp16 B-fragments once, uint4-packed per (wg,kb,lane) ----
    for (int f = tid; f < 32768; f += 256){
        int s   = f & 1;
        int gg  = (f >> 1) & 1;
        int ln  = (f >> 2) & 31;
        int kb  = (f >> 7) & 15;
        int wgf = (f >> 11) & 7;
        int r   = (f >> 14) & 1;
        int g   = r*2 + gg;
        int k   = kb*16 + (ln & 3)*2 + s*8;
        int col = g*HID + h0 + wgf*8 + (ln >> 2);
        sWb[r*16384 + ((wgf*16 + kb)*32 + ln)*4 + gg*2 + s] =
            packh2(Wg[(EMB + k)*GATES + col], Wg[(EMB + k + 1)*GATES + col]);
    }
    // zero sh2 (t=0 initial h state)
    for (int i = tid; i < 2112; i += 256) sh2[i] = 0u;

    int rb0 = gid;              // block-local batch rows this thread owns
    int rb1 = gid + 8;
    int hc0 = wg*8 + qq*2;      // block-local hidden cols (one fp16 pair), 0..63
    int len0 = d_len[b0 + rb0];
    int len1 = d_len[b0 + rb1];
    float c_reg[4] = {0.f,0.f,0.f,0.f};
    float h_reg[4] = {0.f,0.f,0.f,0.f};
    int   wslot = hslot(h0 + hc0);

    // prefetch xz for t=0
    const int row0 = (b0 + rb0)*SEQT;
    const int row1 = (b0 + rb1)*SEQT;
    float4 xzn0, xzn1, xzn2, xzn3;
    {
        int teff = dir ? (SEQT - 1) : 0;
        int id0 = __ldg(&ids[row0 + teff]);
        int id1 = __ldg(&ids[row1 + teff]);
        const float* p0 = &d_proj[id0][dir*GATES];
        const float* p1 = &d_proj[id1][dir*GATES];
        xzn0 = *(const float4*)&p0[(h0 + hc0    )*4];
        xzn1 = *(const float4*)&p0[(h0 + hc0 + 1)*4];
        xzn2 = *(const float4*)&p1[(h0 + hc0    )*4];
        xzn3 = *(const float4*)&p1[(h0 + hc0 + 1)*4];
    }

    asm volatile("barrier.cluster.arrive.aligned;" ::: "memory");

    for (int t = 0; t < SEQT; t++){
        int cur = t & 1, nxt = cur ^ 1;
        int teff = dir ? (SEQT - 1 - t) : t;

        __syncthreads();   // sync1: own h slice (STS'd last step) visible

        // accumulators initialized with prefetched xz (bias + input projection)
        float acc[4][4];
        acc[0][0]=xzn0.x; acc[1][0]=xzn0.y; acc[2][0]=xzn0.z; acc[3][0]=xzn0.w;
        acc[0][1]=xzn1.x; acc[1][1]=xzn1.y; acc[2][1]=xzn1.z; acc[3][1]=xzn1.w;
        acc[0][2]=xzn2.x; acc[1][2]=xzn2.y; acc[2][2]=xzn2.z; acc[3][2]=xzn2.w;
        acc[0][3]=xzn3.x; acc[1][3]=xzn3.y; acc[2][3]=xzn3.z; acc[3][3]=xzn3.w;

        // local-K MMA: our own h slice (k in [rank*64, rank*64+64)) — runs in
        // the arrive->wait skew window, no exchange needed
        #pragma unroll
        for (int j = 0; j < 4; j++)
            mma_kb(acc, sh2, sWb, rank*4 + j, rb0, rb1, qq, wg, lane);

        asm volatile("barrier.cluster.wait.aligned;" ::: "memory");

        // stage the 12 peer kb regions from L2 (16 rows x 3 peers x 8 uint4)
        {
            const uint4* src = (const uint4*)&d_hbuf[dir][cur][b0][0];
            uint4* dst = (uint4*)sh2;
            for (int idx = tid; idx < 384; idx += 256){
                int row = idx / 24;
                int r   = idx % 24;
                int pi  = r >> 3;
                int q   = r & 7;
                int p   = pi + (pi >= rank);
                int o   = row*33 + p*8 + q;
                dst[o] = __ldcg(&src[o]);
            }
        }
        __syncthreads();   // sync2

        // peer-K MMA (12 kb)
        #pragma unroll
        for (int pb = 0; pb < 4; pb++){
            if (pb == rank) continue;
            #pragma unroll
            for (int j = 0; j < 4; j++)
                mma_kb(acc, sh2, sWb, pb*4 + j, rb0, rb1, qq, wg, lane);
        }

        // elementwise LSTM cell (tanh.approx activations)
        {
            bool v0 = (teff < len0);
            bool v1 = (teff < len1);
            #pragma unroll
            for (int ci = 0; ci < 4; ci++){
                float zi = acc[0][ci], zj = acc[1][ci];
                float zf = acc[2][ci], zo = acc[3][ci];
                float nc = c_reg[ci]*sigt(zf + 1.0f) + sigt(zi)*tanha(zj);
                float nh = tanha(nc)*sigt(zo);
                bool v = (ci < 2) ? v0 : v1;
                if (v){ c_reg[ci] = nc; h_reg[ci] = nh; }
            }
        }

        // publish h(t): global L2 for peers, local smem for our own next step
        {
            unsigned u0 = packh2(h_reg[0], h_reg[1]);
            unsigned u1 = packh2(h_reg[2], h_reg[3]);
            d_hbuf[dir][nxt][b0 + rb0][wslot] = u0;
            d_hbuf[dir][nxt][b0 + rb1][wslot] = u1;
            sh2[rb0*132 + wslot] = u0;
            sh2[rb1*132 + wslot] = u1;
        }

        // prefetch next step's xz (flies under arrive + local MMA + wait)
        if (t + 1 < SEQT){
            int tn = dir ? (SEQT - 2 - t) : (t + 1);
            int id0 = __ldg(&ids[row0 + tn]);
            int id1 = __ldg(&ids[row1 + tn]);
            const float* p0 = &d_proj[id0][dir*GATES];
            const float* p1 = &d_proj[id1][dir*GATES];
            xzn0 = *(const float4*)&p0[(h0 + hc0    )*4];
            xzn1 = *(const float4*)&p0[(h0 + hc0 + 1)*4];
            xzn2 = *(const float4*)&p1[(h0 + hc0    )*4];
            xzn3 = *(const float4*)&p1[(h0 + hc0 + 1)*4];
        }

        asm volatile("barrier.cluster.arrive.aligned;" ::: "memory");
    }
    asm volatile("barrier.cluster.wait.aligned;" ::: "memory");

    // write fp32 final hidden state
    d_hfinal[dir][b0 + rb0][h0 + hc0    ] = h_reg[0];
    d_hfinal[dir][b0 + rb0][h0 + hc0 + 1] = h_reg[1];
    d_hfinal[dir][b0 + rb1][h0 + hc0    ] = h_reg[2];
    d_hfinal[dir][b0 + rb1][h0 + hc0 + 1] = h_reg[3];
}

// ---------------------------------------------------------------------------
// Kernel 4: final projection scores = [h_fw | h_bw] @ W_out + b_out
// ---------------------------------------------------------------------------
__global__ void k_out(const float* __restrict__ Wout, const float* __restrict__ bout,
                      float* __restrict__ out){
    int b = blockIdx.x;
    int tid = threadIdx.x;
    float s0 = 0.0f, s1 = 0.0f;
    for (int k = tid; k < 512; k += 256){
        float v = (k < 256) ? d_hfinal[0][b][k] : d_hfinal[1][b][k - 256];
        s0 += v*Wout[2*k];
        s1 += v*Wout[2*k + 1];
    }
    #pragma unroll
    for (int o = 16; o; o >>= 1){
        s0 += __shfl_down_sync(0xffffffffu, s0, o);
        s1 += __shfl_down_sync(0xffffffffu, s1, o);
    }
    __shared__ float r0[8], r1[8];
    int w = tid >> 5;
    if ((tid & 31) == 0){ r0[w] = s0; r1[w] = s1; }
    __syncthreads();
    if (tid == 0){
        float t0 = bout[0], t1 = bout[1];
        #pragma unroll
        for (int i = 0; i < 8; i++){ t0 += r0[i]; t1 += r1[i]; }
        out[2*b]     = t0;
        out[2*b + 1] = t1;
    }
}

// ---------------------------------------------------------------------------
extern "C" void kernel_launch(void* const* d_in, const int* in_sizes, int n_in,
                              void* d_out, int out_size){
    const int*   ids  = (const int*)  d_in[0];
    const float* emb  = (const float*)d_in[1];
    const float* Wfw  = (const float*)d_in[2];
    const float* bfw  = (const float*)d_in[3];
    const float* Wbw  = (const float*)d_in[4];
    const float* bbw  = (const float*)d_in[5];
    const float* Wout = (const float*)d_in[6];
    const float* bout = (const float*)d_in[7];
    float* out = (float*)d_out;

    cudaFuncSetAttribute(k_rnn, cudaFuncAttributeMaxDynamicSharedMemorySize, SMEM_RNN);

    k_init<<<BATCH, 128>>>(ids);
    dim3 g2(16, (VOCAB + 127)/128);
    k_vgemm<<<g2, 256>>>(emb, Wfw, bfw, Wbw, bbw);
    k_rnn<<<NBLK, 256, SMEM_RNN>>>(Wfw, Wbw, ids);
    k_out<<<BATCH, 256>>>(Wout, bout, out);
}

// round 11
// speedup vs baseline: 1.1395x; 1.1395x over previous
#include <cuda_runtime.h>
#include <cuda_fp16.h>
#include <math.h>

#define BATCH 256
#define SEQT  512
#define VOCAB 50000
#define EMB   300
#define HID   256
#define GATES 1024   // 4*HID
#define NBLK  128
// sWb (32768 u32 = 128KB fp16 frags) + sh2 (16*132 u32)
#define SMEM_RNN (32768*4 + 2112*4)

// Scratch (static device memory — allocation-free)
__device__ float    d_proj[VOCAB][2*GATES];    // [v][dir*1024 + hc*4 + g], bias folded in
__device__ unsigned d_hbuf[2][2][BATCH][132];  // fp16 pairs, k-permuted
__device__ float    d_hfinal[2][BATCH][HID];   // fp32 final hidden state
__device__ int      d_len[BATCH];

__device__ __forceinline__ float tanha(float x){
    float y; asm("tanh.approx.f32 %0, %1;" : "=f"(y) : "f"(x)); return y;
}
__device__ __forceinline__ float sigt(float x){
    return fmaf(tanha(0.5f*x), 0.5f, 0.5f);
}
// pair-permutation inside a 16-k block: pair j -> slot (j&3)*2 + (j>>2)
__device__ __forceinline__ int hslot(int k){   // k even; returns u32 index
    int blk = k >> 4, j = (k & 15) >> 1;
    return blk*8 + (j & 3)*2 + (j >> 2);
}
__device__ __forceinline__ unsigned packh2(float a, float b){
    __half2 hv = __halves2half2(__float2half_rn(a), __float2half_rn(b));
    return *(unsigned*)&hv;
}
__device__ __forceinline__ void cp16(unsigned dst_smem, const void* src, int szbytes){
    asm volatile("cp.async.cg.shared.global [%0], [%1], 16, %2;"
                 :: "r"(dst_smem), "l"(src), "r"(szbytes));
}

// ---------------------------------------------------------------------------
// Kernel 1: lengths + zero initial (permuted-fp16) h states
// ---------------------------------------------------------------------------
__global__ void k_init(const int* __restrict__ ids){
    int b = blockIdx.x;
    __shared__ int cnt;
    if (threadIdx.x == 0) cnt = 0;
    __syncthreads();
    int c = 0;
    for (int t = threadIdx.x; t < SEQT; t += blockDim.x)
        c += (ids[b*SEQT + t] != 0);
    #pragma unroll
    for (int o = 16; o; o >>= 1) c += __shfl_down_sync(0xffffffffu, c, o);
    if ((threadIdx.x & 31) == 0) atomicAdd(&cnt, c);
    __syncthreads();
    if (threadIdx.x == 0) d_len[b] = cnt;
    for (int i = threadIdx.x; i < 132; i += blockDim.x){
        d_hbuf[0][0][b][i] = 0u;
        d_hbuf[0][1][b][i] = 0u;
        d_hbuf[1][0][b][i] = 0u;
        d_hbuf[1][1][b][i] = 0u;
    }
}

// ---------------------------------------------------------------------------
// Kernel 2: vocab projection GEMM via tf32 mma with cp.async double-buffered
// smem pipeline. A stored [m][20] row-major, B stored [k][132]. Raw fp32 bits
// feed the tf32 mma (HW truncates mantissa).
// ---------------------------------------------------------------------------
#define NIT 19   // ceil(304/16)
__global__ void __launch_bounds__(256, 2)
k_vgemm(const float* __restrict__ emb,
        const float* __restrict__ Wfw, const float* __restrict__ bfw,
        const float* __restrict__ Wbw, const float* __restrict__ bbw){
    __shared__ float As[2][128][20];     // [buf][m][k] rows 80B (16B-aligned)
    __shared__ float Bs[2][16][132];     // [buf][k][n]
    int nx  = blockIdx.x;
    int dir = nx >> 3;
    int n0  = (nx & 7) * 128;
    int m0  = blockIdx.y * 128;
    const float* __restrict__ Wg = dir ? Wbw : Wfw;
    const float* __restrict__ bg = dir ? bbw : bfw;

    int t    = threadIdx.x;
    int lane = t & 31;
    int w    = t >> 5;
    int wm   = w & 1;
    int wn   = w >> 1;

    unsigned sA = (unsigned)__cvta_generic_to_shared(&As[0][0][0]);
    unsigned sB = (unsigned)__cvta_generic_to_shared(&Bs[0][0][0]);

    // async-load one 16-k stage into buffer bf
    auto load_stage = [&](int it, int bf){
        int k0 = it*16;
        #pragma unroll
        for (int i = 0; i < 2; i++){
            int idx = t + i*256;           // 0..511
            int m   = idx >> 2;
            int kk4 = (idx & 3)*4;
            int gm  = m0 + m;
            int ok  = (gm < VOCAB && (k0 + kk4) < EMB) ? 16 : 0;
            const float* src = &emb[(size_t)gm*EMB + k0 + kk4];
            if (gm >= VOCAB) src = emb;    // keep address in-range
            cp16(sA + (unsigned)(bf*128*20 + m*20 + kk4)*4u, src, ok);
        }
        #pragma unroll
        for (int i = 0; i < 2; i++){
            int idx = t + i*256;           // 0..511
            int kk  = idx >> 5;            // 0..15
            int nn4 = (idx & 31)*4;        // 0..124
            int ok  = (k0 + kk < EMB) ? 16 : 0;
            const float* src = &Wg[(size_t)(k0 + kk)*GATES + n0 + nn4];
            if (k0 + kk >= EMB) src = Wg;
            cp16(sB + (unsigned)(bf*16*132 + kk*132 + nn4)*4u, src, ok);
        }
        asm volatile("cp.async.commit_group;" ::: "memory");
    };

    float acc[4][4][4] = {};

    load_stage(0, 0);
    for (int it = 0; it < NIT; it++){
        int bf = it & 1;
        if (it + 1 < NIT){
            load_stage(it + 1, bf ^ 1);
            asm volatile("cp.async.wait_group 1;" ::: "memory");
        } else {
            asm volatile("cp.async.wait_group 0;" ::: "memory");
        }
        __syncthreads();

        #pragma unroll
        for (int k8 = 0; k8 < 2; k8++){
            int k = k8*8 + (lane & 3);
            unsigned a[4][4], b[4][2];
            #pragma unroll
            for (int mi = 0; mi < 4; mi++){
                int row = wm*64 + mi*16 + (lane >> 2);
                a[mi][0] = __float_as_uint(As[bf][row    ][k]);
                a[mi][1] = __float_as_uint(As[bf][row + 8][k]);
                a[mi][2] = __float_as_uint(As[bf][row    ][k + 4]);
                a[mi][3] = __float_as_uint(As[bf][row + 8][k + 4]);
            }
            #pragma unroll
            for (int ni = 0; ni < 4; ni++){
                int n = wn*32 + ni*8 + (lane >> 2);
                b[ni][0] = __float_as_uint(Bs[bf][k    ][n]);
                b[ni][1] = __float_as_uint(Bs[bf][k + 4][n]);
            }
            #pragma unroll
            for (int mi = 0; mi < 4; mi++)
                #pragma unroll
                for (int ni = 0; ni < 4; ni++)
                    asm volatile(
                        "mma.sync.aligned.m16n8k8.row.col.f32.tf32.tf32.f32 "
                        "{%0,%1,%2,%3},{%4,%5,%6,%7},{%8,%9},{%0,%1,%2,%3};"
                        : "+f"(acc[mi][ni][0]), "+f"(acc[mi][ni][1]),
                          "+f"(acc[mi][ni][2]), "+f"(acc[mi][ni][3])
                        : "r"(a[mi][0]), "r"(a[mi][1]), "r"(a[mi][2]), "r"(a[mi][3]),
                          "r"(b[ni][0]), "r"(b[ni][1]));
        }
        __syncthreads();
    }

    #pragma unroll
    for (int mi = 0; mi < 4; mi++){
        int rbase = m0 + wm*64 + mi*16 + (lane >> 2);
        #pragma unroll
        for (int ni = 0; ni < 4; ni++){
            int cbase = n0 + wn*32 + ni*8 + (lane & 3)*2;
            #pragma unroll
            for (int c = 0; c < 4; c++){
                int gm  = rbase + (c >> 1)*8;
                int col = cbase + (c & 1);
                if (gm >= VOCAB) continue;
                int g  = col >> 8;
                int hc = col & 255;
                d_proj[gm][dir*GATES + hc*4 + g] = acc[mi][ni][c] + bg[col];
            }
        }
    }
}

// ---------------------------------------------------------------------------
// Kernel 3: persistent bidirectional LSTM — EXACT R9 skeleton (2645.6us):
// cluster(4), 128 blocks = 2 dirs x 16 batch-tiles(16 rows) x 4 hid-tiles
// (64 cols), full staging after the wait, single MMA loop.
// ---------------------------------------------------------------------------
__global__ void __launch_bounds__(256, 1) __cluster_dims__(4, 1, 1)
k_rnn(const float* __restrict__ Wfw, const float* __restrict__ Wbw,
      const int* __restrict__ ids){
    extern __shared__ unsigned smem_u[];
    unsigned* sWb = smem_u;            // 2 regions x [wg 0..7][kb][lane] uint4 fp16 B frags
    unsigned* sh2 = smem_u + 32768;    // [16][132] fp16 pairs, k-permuted

    int tid = threadIdx.x;
    int bid = blockIdx.x;
    int dir = bid >> 6;
    int tl  = bid & 63;
    int b0  = (tl >> 2) * 16;          // batch tile (16 rows)
    int h0  = (tl & 3) * 64;           // hid tile (64 cols) == cluster rank * 64
    const float* __restrict__ Wg = dir ? Wbw : Wfw;

    int lane = tid & 31;
    int wg   = tid >> 5;    // warp id = hid group of 8 (0..7)
    int gid  = lane >> 2;
    int qq   = lane & 3;

    // ---- Fill Wh fp16 B-fragments once, uint4-packed per (wg,kb,lane) ----
    // region r holds gates (2r, 2r+1): uint4 = {g.s0, g.s1, (g+1).s0, (g+1).s1}
    for (int f = tid; f < 32768; f += 256){
        int s   = f & 1;
        int gg  = (f >> 1) & 1;
        int ln  = (f >> 2) & 31;
        int kb  = (f >> 7) & 15;
        int wgf = (f >> 11) & 7;
        int r   = (f >> 14) & 1;
        int g   = r*2 + gg;
        int k   = kb*16 + (ln & 3)*2 + s*8;
        int col = g*HID + h0 + wgf*8 + (ln >> 2);
        sWb[r*16384 + ((wgf*16 + kb)*32 + ln)*4 + gg*2 + s] =
            packh2(Wg[(EMB + k)*GATES + col], Wg[(EMB + k + 1)*GATES + col]);
    }

    int rb0 = gid;              // block-local batch rows this thread owns
    int rb1 = gid + 8;
    int hc0 = wg*8 + qq*2;      // block-local hidden cols (one fp16 pair), 0..63
    int len0 = d_len[b0 + rb0];
    int len1 = d_len[b0 + rb1];
    float c_reg[4] = {0.f,0.f,0.f,0.f};
    float h_reg[4] = {0.f,0.f,0.f,0.f};
    int   wslot = hslot(h0 + hc0);

    // prefetch xz for t=0
    const int row0 = (b0 + rb0)*SEQT;
    const int row1 = (b0 + rb1)*SEQT;
    float4 xzn0, xzn1, xzn2, xzn3;
    {
        int teff = dir ? (SEQT - 1) : 0;
        int id0 = __ldg(&ids[row0 + teff]);
        int id1 = __ldg(&ids[row1 + teff]);
        const float* p0 = &d_proj[id0][dir*GATES];
        const float* p1 = &d_proj[id1][dir*GATES];
        xzn0 = *(const float4*)&p0[(h0 + hc0    )*4];
        xzn1 = *(const float4*)&p0[(h0 + hc0 + 1)*4];
        xzn2 = *(const float4*)&p1[(h0 + hc0    )*4];
        xzn3 = *(const float4*)&p1[(h0 + hc0 + 1)*4];
    }

    asm volatile("barrier.cluster.arrive.aligned;" ::: "memory");

    for (int t = 0; t < SEQT; t++){
        int cur = t & 1, nxt = cur ^ 1;
        int teff = dir ? (SEQT - 1 - t) : t;

        asm volatile("barrier.cluster.wait.aligned;" ::: "memory");

        // stage current h: flat contiguous copy (16 rows x 132 u32 = 528 uint4)
        {
            const uint4* src = (const uint4*)&d_hbuf[dir][cur][b0][0];
            uint4* dst = (uint4*)sh2;
            dst[tid]       = __ldcg(&src[tid]);
            dst[tid + 256] = __ldcg(&src[tid + 256]);
            if (tid < 16) dst[tid + 512] = __ldcg(&src[tid + 512]);
        }
        __syncthreads();

        // accumulators initialized with prefetched xz (bias + input projection)
        float acc[4][4];
        acc[0][0]=xzn0.x; acc[1][0]=xzn0.y; acc[2][0]=xzn0.z; acc[3][0]=xzn0.w;
        acc[0][1]=xzn1.x; acc[1][1]=xzn1.y; acc[2][1]=xzn1.z; acc[3][1]=xzn1.w;
        acc[0][2]=xzn2.x; acc[1][2]=xzn2.y; acc[2][2]=xzn2.z; acc[3][2]=xzn2.w;
        acc[0][3]=xzn3.x; acc[1][3]=xzn3.y; acc[2][3]=xzn3.z; acc[3][3]=xzn3.w;

        #pragma unroll
        for (int kb = 0; kb < 16; kb++){
            uint2 aA = *(const uint2*)&sh2[rb0*132 + kb*8 + qq*2];
            uint2 aB = *(const uint2*)&sh2[rb1*132 + kb*8 + qq*2];
            uint4 B01 = *(const uint4*)&sWb[        ((wg*16 + kb)*32 + lane)*4];
            uint4 B23 = *(const uint4*)&sWb[16384 + ((wg*16 + kb)*32 + lane)*4];
            asm volatile(
                "mma.sync.aligned.m16n8k16.row.col.f32.f16.f16.f32 "
                "{%0,%1,%2,%3},{%4,%5,%6,%7},{%8,%9},{%0,%1,%2,%3};"
                : "+f"(acc[0][0]), "+f"(acc[0][1]), "+f"(acc[0][2]), "+f"(acc[0][3])
                : "r"(aA.x), "r"(aB.x), "r"(aA.y), "r"(aB.y), "r"(B01.x), "r"(B01.y));
            asm volatile(
                "mma.sync.aligned.m16n8k16.row.col.f32.f16.f16.f32 "
                "{%0,%1,%2,%3},{%4,%5,%6,%7},{%8,%9},{%0,%1,%2,%3};"
                : "+f"(acc[1][0]), "+f"(acc[1][1]), "+f"(acc[1][2]), "+f"(acc[1][3])
                : "r"(aA.x), "r"(aB.x), "r"(aA.y), "r"(aB.y), "r"(B01.z), "r"(B01.w));
            asm volatile(
                "mma.sync.aligned.m16n8k16.row.col.f32.f16.f16.f32 "
                "{%0,%1,%2,%3},{%4,%5,%6,%7},{%8,%9},{%0,%1,%2,%3};"
                : "+f"(acc[2][0]), "+f"(acc[2][1]), "+f"(acc[2][2]), "+f"(acc[2][3])
                : "r"(aA.x), "r"(aB.x), "r"(aA.y), "r"(aB.y), "r"(B23.x), "r"(B23.y));
            asm volatile(
                "mma.sync.aligned.m16n8k16.row.col.f32.f16.f16.f32 "
                "{%0,%1,%2,%3},{%4,%5,%6,%7},{%8,%9},{%0,%1,%2,%3};"
                : "+f"(acc[3][0]), "+f"(acc[3][1]), "+f"(acc[3][2]), "+f"(acc[3][3])
                : "r"(aA.x), "r"(aB.x), "r"(aA.y), "r"(aB.y), "r"(B23.z), "r"(B23.w));
        }

        // elementwise LSTM cell (tanh.approx activations)
        {
            bool v0 = (teff < len0);
            bool v1 = (teff < len1);
            #pragma unroll
            for (int ci = 0; ci < 4; ci++){
                float zi = acc[0][ci], zj = acc[1][ci];
                float zf = acc[2][ci], zo = acc[3][ci];
                float nc = c_reg[ci]*sigt(zf + 1.0f) + sigt(zi)*tanha(zj);
                float nh = tanha(nc)*sigt(zo);
                bool v = (ci < 2) ? v0 : v1;
                if (v){ c_reg[ci] = nc; h_reg[ci] = nh; }
            }
        }

        // write new h pairs to the global exchange buffer (L2)
        d_hbuf[dir][nxt][b0 + rb0][wslot] = packh2(h_reg[0], h_reg[1]);
        d_hbuf[dir][nxt][b0 + rb1][wslot] = packh2(h_reg[2], h_reg[3]);

        // prefetch next step's xz (flies under barrier + next stage + MMA)
        if (t + 1 < SEQT){
            int tn = dir ? (SEQT - 2 - t) : (t + 1);
            int id0 = __ldg(&ids[row0 + tn]);
            int id1 = __ldg(&ids[row1 + tn]);
            const float* p0 = &d_proj[id0][dir*GATES];
            const float* p1 = &d_proj[id1][dir*GATES];
            xzn0 = *(const float4*)&p0[(h0 + hc0    )*4];
            xzn1 = *(const float4*)&p0[(h0 + hc0 + 1)*4];
            xzn2 = *(const float4*)&p1[(h0 + hc0    )*4];
            xzn3 = *(const float4*)&p1[(h0 + hc0 + 1)*4];
        }

        asm volatile("barrier.cluster.arrive.aligned;" ::: "memory");
    }
    asm volatile("barrier.cluster.wait.aligned;" ::: "memory");

    // write fp32 final hidden state
    d_hfinal[dir][b0 + rb0][h0 + hc0    ] = h_reg[0];
    d_hfinal[dir][b0 + rb0][h0 + hc0 + 1] = h_reg[1];
    d_hfinal[dir][b0 + rb1][h0 + hc0    ] = h_reg[2];
    d_hfinal[dir][b0 + rb1][h0 + hc0 + 1] = h_reg[3];
}

// ---------------------------------------------------------------------------
// Kernel 4: final projection scores = [h_fw | h_bw] @ W_out + b_out
// ---------------------------------------------------------------------------
__global__ void k_out(const float* __restrict__ Wout, const float* __restrict__ bout,
                      float* __restrict__ out){
    int b = blockIdx.x;
    int tid = threadIdx.x;
    float s0 = 0.0f, s1 = 0.0f;
    for (int k = tid; k < 512; k += 256){
        float v = (k < 256) ? d_hfinal[0][b][k] : d_hfinal[1][b][k - 256];
        s0 += v*Wout[2*k];
        s1 += v*Wout[2*k + 1];
    }
    #pragma unroll
    for (int o = 16; o; o >>= 1){
        s0 += __shfl_down_sync(0xffffffffu, s0, o);
        s1 += __shfl_down_sync(0xffffffffu, s1, o);
    }
    __shared__ float r0[8], r1[8];
    int w = tid >> 5;
    if ((tid & 31) == 0){ r0[w] = s0; r1[w] = s1; }
    __syncthreads();
    if (tid == 0){
        float t0 = bout[0], t1 = bout[1];
        #pragma unroll
        for (int i = 0; i < 8; i++){ t0 += r0[i]; t1 += r1[i]; }
        out[2*b]     = t0;
        out[2*b + 1] = t1;
    }
}

// ---------------------------------------------------------------------------
extern "C" void kernel_launch(void* const* d_in, const int* in_sizes, int n_in,
                              void* d_out, int out_size){
    const int*   ids  = (const int*)  d_in[0];
    const float* emb  = (const float*)d_in[1];
    const float* Wfw  = (const float*)d_in[2];
    const float* bfw  = (const float*)d_in[3];
    const float* Wbw  = (const float*)d_in[4];
    const float* bbw  = (const float*)d_in[5];
    const float* Wout = (const float*)d_in[6];
    const float* bout = (const float*)d_in[7];
    float* out = (float*)d_out;

    cudaFuncSetAttribute(k_rnn, cudaFuncAttributeMaxDynamicSharedMemorySize, SMEM_RNN);

    k_init<<<BATCH, 128>>>(ids);
    dim3 g2(16, (VOCAB + 127)/128);
    k_vgemm<<<g2, 256>>>(emb, Wfw, bfw, Wbw, bbw);
    k_rnn<<<NBLK, 256, SMEM_RNN>>>(Wfw, Wbw, ids);
    k_out<<<BATCH, 256>>>(Wout, bout, out);
}